// round 2
// baseline (speedup 1.0000x reference)
#include <cuda_runtime.h>
#include <stdint.h>

// Problem dims
#define BB 4
#define SS 2048
#define DD 768
#define DQ 64
#define HH 3072
#define RR 8192   // BB*SS

// ---------------- scratch (device globals; no allocation allowed) ----------
__device__ float g_h [RR*DD];
__device__ float g_h2[RR*DD];
__device__ float g_y1[RR*DD];
__device__ float g_q [RR*DQ];
__device__ float g_k [RR*DQ];
__device__ float g_v [RR*DQ];
__device__ float g_oh[RR*DQ];
__device__ float g_S [(long long)BB*SS*SS];
__device__ float g_P [(long long)BB*SS*SS];
__device__ float g_a1[(long long)RR*HH];
__device__ float g_ws[DQ*DD];

__device__ __forceinline__ float to_tf32(float x) {
    float r;
    asm("cvt.rna.tf32.f32 %0, %1;\n" : "=f"(r) : "f"(x));
    return r;
}

// ---------------- block reductions (256 threads) ---------------------------
__device__ __forceinline__ float blk_sum(float v) {
    __shared__ float sm[9];
    #pragma unroll
    for (int o = 16; o; o >>= 1) v += __shfl_xor_sync(0xffffffffu, v, o);
    if ((threadIdx.x & 31) == 0) sm[threadIdx.x >> 5] = v;
    __syncthreads();
    if (threadIdx.x == 0) {
        float t = 0.f;
        #pragma unroll
        for (int i = 0; i < 8; i++) t += sm[i];
        sm[8] = t;
    }
    __syncthreads();
    float r = sm[8];
    __syncthreads();
    return r;
}

__device__ __forceinline__ float blk_max(float v) {
    __shared__ float sm[9];
    #pragma unroll
    for (int o = 16; o; o >>= 1) v = fmaxf(v, __shfl_xor_sync(0xffffffffu, v, o));
    if ((threadIdx.x & 31) == 0) sm[threadIdx.x >> 5] = v;
    __syncthreads();
    if (threadIdx.x == 0) {
        float t = -3.0e38f;
        #pragma unroll
        for (int i = 0; i < 8; i++) t = fmaxf(t, sm[i]);
        sm[8] = t;
    }
    __syncthreads();
    float r = sm[8];
    __syncthreads();
    return r;
}

// ---------------- small kernels --------------------------------------------
// W_sum[k][n] = sum_h lin_w[h*64 + k][n]   (tile-concat collapse)
__global__ void wsum_kernel(const float* __restrict__ w, float* __restrict__ d) {
    int i = blockIdx.x * blockDim.x + threadIdx.x;
    if (i >= DQ * DD) return;
    int k = i / DD, n = i % DD;
    float s = 0.f;
    #pragma unroll
    for (int h = 0; h < 12; h++) s += w[(h * DQ + k) * DD + n];
    d[i] = s;
}

// LayerNorm over 768 cols, fp32 -> fp32. One block / row, 256 threads.
__global__ void ln_kernel(const float* __restrict__ x, const float* __restrict__ g,
                          const float* __restrict__ b, float* __restrict__ o) {
    long long row = blockIdx.x;
    const float* xr = x + row * DD;
    int t = threadIdx.x;
    float v0 = xr[t], v1 = xr[t + 256], v2 = xr[t + 512];
    float mu = blk_sum(v0 + v1 + v2) * (1.f / 768.f);
    float d0 = v0 - mu, d1 = v1 - mu, d2 = v2 - mu;
    float var = blk_sum(d0 * d0 + d1 * d1 + d2 * d2) * (1.f / 768.f);
    float rs = rsqrtf(var + 1e-5f);
    float* orow = o + row * DD;
    orow[t]       = d0 * rs * g[t]       + b[t];
    orow[t + 256] = d1 * rs * g[t + 256] + b[t + 256];
    orow[t + 512] = d2 * rs * g[t + 512] + b[t + 512];
}

// softmax over 2048 cols of S*0.125, fp32 -> fp32 probs.
__global__ void softmax_kernel(const float* __restrict__ S, float* __restrict__ P) {
    long long row = blockIdx.x;
    const float* sr = S + row * SS;
    float* pr = P + row * SS;
    int t = threadIdx.x;
    float v[8];
    float m = -3.0e38f;
    #pragma unroll
    for (int i = 0; i < 8; i++) { v[i] = sr[t + i * 256] * 0.125f; m = fmaxf(m, v[i]); }
    m = blk_max(m);
    float s = 0.f;
    #pragma unroll
    for (int i = 0; i < 8; i++) { v[i] = __expf(v[i] - m); s += v[i]; }
    s = blk_sum(s);
    float inv = 1.f / s;
    #pragma unroll
    for (int i = 0; i < 8; i++) pr[t + i * 256] = v[i] * inv;
}

// ---------------- tf32 mma.sync GEMM ---------------------------------------
__device__ __forceinline__ void mma_tf32(float* c, const uint32_t* a, const uint32_t* b) {
    asm volatile(
        "mma.sync.aligned.m16n8k8.row.col.f32.tf32.tf32.f32 "
        "{%0,%1,%2,%3}, {%4,%5,%6,%7}, {%8,%9}, {%0,%1,%2,%3};\n"
        : "+f"(c[0]), "+f"(c[1]), "+f"(c[2]), "+f"(c[3])
        : "r"(a[0]), "r"(a[1]), "r"(a[2]), "r"(a[3]), "r"(b[0]), "r"(b[1]));
}

// C[M,N] = A[M,K] (row-major) x B.  BTRANS=1: B stored [N,K].  BTRANS=0: B [K,N].
// EPI: 0 plain f32 store, 2 f32 = acc + bias[c] + res, 3 f32 = gelu(acc+bias[c]).
// BM=BN=128, BK=32, 256 threads = 8 warps (2x4) each owning a 64x32 sub-tile.
// Requirements (all call sites): M%128==0, K%32==0, N%8==0 (zero-guarded above N).
template<int BTRANS, int EPI>
__global__ __launch_bounds__(256, 2) void gemm_kernel(
    const float* __restrict__ A, const float* __restrict__ Bm,
    float* __restrict__ Cm, const float* __restrict__ bias, const float* __restrict__ res,
    int M, int N, int K, int lda, int ldb, int ldc,
    long long sA, long long sB, long long sC)
{
    A  += (long long)blockIdx.z * sA;
    Bm += (long long)blockIdx.z * sB;
    const long long coff = (long long)blockIdx.z * sC;

    __shared__ float As[128 * 36];              // [m][k], stride 36
    __shared__ float Bs[128 * 36];              // BTRANS: [n][k] stride 36; else [k][n] stride 136

    const int tid  = threadIdx.x;
    const int lane = tid & 31;
    const int warp = tid >> 5;
    const int wm = (warp >> 2) * 64, wn = (warp & 3) * 32;
    const int grp = lane >> 2, tg = lane & 3;
    const int bm = blockIdx.y * 128, bn = blockIdx.x * 128;

    float acc[4][4][4];
    #pragma unroll
    for (int i = 0; i < 4; i++)
        #pragma unroll
        for (int j = 0; j < 4; j++)
            #pragma unroll
            for (int l = 0; l < 4; l++) acc[i][j][l] = 0.f;

    const int ar = tid >> 3;            // 0..31
    const int ac = (tid & 7) * 4;       // 0..28

    for (int k0 = 0; k0 < K; k0 += 32) {
        // ---- A tile 128x32 (f32 -> tf32-rounded)
        #pragma unroll
        for (int p = 0; p < 4; p++) {
            int row = ar + 32 * p;
            float4 v = *(const float4*)(A + (long long)(bm + row) * lda + (k0 + ac));
            float4 w = make_float4(to_tf32(v.x), to_tf32(v.y), to_tf32(v.z), to_tf32(v.w));
            *(float4*)&As[row * 36 + ac] = w;
        }
        // ---- B tile
        if (BTRANS) {
            // B is [N,K] row-major -> Bs[n][k]
            #pragma unroll
            for (int p = 0; p < 4; p++) {
                int n = ar + 32 * p;
                float4 v = make_float4(0.f, 0.f, 0.f, 0.f);
                if (bn + n < N)
                    v = *(const float4*)(Bm + (long long)(bn + n) * ldb + (k0 + ac));
                *(float4*)&Bs[n * 36 + ac] = make_float4(to_tf32(v.x), to_tf32(v.y), to_tf32(v.z), to_tf32(v.w));
            }
        } else {
            // B is [K,N] row-major -> Bs[k][n], stride 136
            const int n4 = (tid & 31) * 4;  // 0..124
            const int kr = tid >> 5;        // 0..7
            #pragma unroll
            for (int p = 0; p < 4; p++) {
                int kk = kr + 8 * p;
                float4 v = make_float4(0.f, 0.f, 0.f, 0.f);
                if (bn + n4 < N)
                    v = *(const float4*)(Bm + (long long)(k0 + kk) * ldb + (bn + n4));
                *(float4*)&Bs[kk * 136 + n4] = make_float4(to_tf32(v.x), to_tf32(v.y), to_tf32(v.z), to_tf32(v.w));
            }
        }
        __syncthreads();

        #pragma unroll
        for (int ks = 0; ks < 32; ks += 8) {
            uint32_t af[4][4], bfr[4][2];
            #pragma unroll
            for (int mi = 0; mi < 4; mi++) {
                int r = wm + mi * 16 + grp;
                af[mi][0] = __float_as_uint(As[r * 36 + ks + tg]);
                af[mi][1] = __float_as_uint(As[(r + 8) * 36 + ks + tg]);
                af[mi][2] = __float_as_uint(As[r * 36 + ks + tg + 4]);
                af[mi][3] = __float_as_uint(As[(r + 8) * 36 + ks + tg + 4]);
            }
            #pragma unroll
            for (int ni = 0; ni < 4; ni++) {
                int c = wn + ni * 8 + grp;
                if (BTRANS) {
                    bfr[ni][0] = __float_as_uint(Bs[c * 36 + ks + tg]);
                    bfr[ni][1] = __float_as_uint(Bs[c * 36 + ks + tg + 4]);
                } else {
                    bfr[ni][0] = __float_as_uint(Bs[(ks + tg) * 136 + c]);
                    bfr[ni][1] = __float_as_uint(Bs[(ks + tg + 4) * 136 + c]);
                }
            }
            #pragma unroll
            for (int mi = 0; mi < 4; mi++)
                #pragma unroll
                for (int ni = 0; ni < 4; ni++)
                    mma_tf32(acc[mi][ni], af[mi], bfr[ni]);
        }
        __syncthreads();
    }

    // ---- epilogue
    #pragma unroll
    for (int mi = 0; mi < 4; mi++) {
        #pragma unroll
        for (int ni = 0; ni < 4; ni++) {
            int c = bn + wn + ni * 8 + 2 * tg;
            if (c >= N) continue;
            #pragma unroll
            for (int rr2 = 0; rr2 < 2; rr2++) {
                int r = bm + wm + mi * 16 + grp + rr2 * 8;
                float v0 = acc[mi][ni][rr2 * 2], v1 = acc[mi][ni][rr2 * 2 + 1];
                long long off = coff + (long long)r * ldc + c;
                if (EPI == 0) {
                    Cm[off] = v0; Cm[off + 1] = v1;
                } else if (EPI == 2) {
                    Cm[off]     = v0 + bias[c]     + res[off];
                    Cm[off + 1] = v1 + bias[c + 1] + res[off + 1];
                } else {
                    float x0 = v0 + bias[c], x1 = v1 + bias[c + 1];
                    Cm[off]     = 0.5f * x0 * (1.f + erff(x0 * 0.7071067811865475f));
                    Cm[off + 1] = 0.5f * x1 * (1.f + erff(x1 * 0.7071067811865475f));
                }
            }
        }
    }
}

// ---------------- launch ----------------------------------------------------
extern "C" void kernel_launch(void* const* d_in, const int* in_sizes, int n_in,
                              void* d_out, int out_size) {
    const float* x    = (const float*)d_in[0];
    const float* wq   = (const float*)d_in[1];
    const float* wk   = (const float*)d_in[2];
    const float* wv   = (const float*)d_in[3];
    const float* linw = (const float*)d_in[4];
    const float* linb = (const float*)d_in[5];
    const float* ln1g = (const float*)d_in[6];
    const float* ln1b = (const float*)d_in[7];
    const float* f1w  = (const float*)d_in[8];
    const float* f1b  = (const float*)d_in[9];
    const float* f2w  = (const float*)d_in[10];
    const float* f2b  = (const float*)d_in[11];
    float* out = (float*)d_out;

    void *p_h, *p_h2, *p_y1, *p_q, *p_k, *p_v, *p_oh, *p_S, *p_P, *p_a1, *p_ws;
    cudaGetSymbolAddress(&p_h,  g_h);
    cudaGetSymbolAddress(&p_h2, g_h2);
    cudaGetSymbolAddress(&p_y1, g_y1);
    cudaGetSymbolAddress(&p_q,  g_q);
    cudaGetSymbolAddress(&p_k,  g_k);
    cudaGetSymbolAddress(&p_v,  g_v);
    cudaGetSymbolAddress(&p_oh, g_oh);
    cudaGetSymbolAddress(&p_S,  g_S);
    cudaGetSymbolAddress(&p_P,  g_P);
    cudaGetSymbolAddress(&p_a1, g_a1);
    cudaGetSymbolAddress(&p_ws, g_ws);

    #define FP(p) ((float*)(p))
    dim3 blk(256);

    // W_sum (tile-concat collapse of lin_w)
    wsum_kernel<<<(DQ * DD + 255) / 256, blk>>>(linw, FP(p_ws));

    // LN1: x -> h
    ln_kernel<<<RR, blk>>>(x, ln1g, ln1b, FP(p_h));

    // Q, K, V = h @ w*   [8192,768]x[768,64]
    gemm_kernel<0, 0><<<dim3(1, 64, 1), blk>>>(FP(p_h), wq, FP(p_q), nullptr, nullptr,
        RR, DQ, DD, DD, DQ, DQ, 0, 0, 0);
    gemm_kernel<0, 0><<<dim3(1, 64, 1), blk>>>(FP(p_h), wk, FP(p_k), nullptr, nullptr,
        RR, DQ, DD, DD, DQ, DQ, 0, 0, 0);
    gemm_kernel<0, 0><<<dim3(1, 64, 1), blk>>>(FP(p_h), wv, FP(p_v), nullptr, nullptr,
        RR, DQ, DD, DD, DQ, DQ, 0, 0, 0);

    // S = q @ k^T  per batch  [2048,64]x[64,2048]
    gemm_kernel<1, 0><<<dim3(16, 16, 4), blk>>>(FP(p_q), FP(p_k), FP(p_S), nullptr, nullptr,
        SS, SS, DQ, DQ, DQ, SS,
        (long long)SS * DQ, (long long)SS * DQ, (long long)SS * SS);

    // P = softmax(S/8)
    softmax_kernel<<<RR, blk>>>(FP(p_S), FP(p_P));

    // out_head = P @ v  per batch  [2048,2048]x[2048,64]
    gemm_kernel<0, 0><<<dim3(1, 16, 4), blk>>>(FP(p_P), FP(p_v), FP(p_oh), nullptr, nullptr,
        SS, DQ, SS, SS, DQ, DQ,
        (long long)SS * SS, (long long)SS * DQ, (long long)SS * DQ);

    // y1 = out_head @ W_sum + lin_b + x
    gemm_kernel<0, 2><<<dim3(6, 64, 1), blk>>>(FP(p_oh), FP(p_ws), FP(p_y1), linb, x,
        RR, DD, DQ, DQ, DD, DD, 0, 0, 0);

    // LN2 (reuses ln1 params, matching reference): y1 -> h2
    ln_kernel<<<RR, blk>>>(FP(p_y1), ln1g, ln1b, FP(p_h2));

    // a1 = gelu(h2 @ fc1_w + fc1_b)
    gemm_kernel<0, 3><<<dim3(24, 64, 1), blk>>>(FP(p_h2), f1w, FP(p_a1), f1b, nullptr,
        RR, HH, DD, DD, HH, HH, 0, 0, 0);

    // out = a1 @ fc2_w + fc2_b + y1
    gemm_kernel<0, 2><<<dim3(6, 64, 1), blk>>>(FP(p_a1), f2w, out, f2b, FP(p_y1),
        RR, DD, HH, HH, DD, DD, 0, 0, 0);
    #undef FP
}

// round 3
// speedup vs baseline: 1.3594x; 1.3594x over previous
#include <cuda_runtime.h>
#include <stdint.h>

// Problem dims
#define BB 4
#define SS 2048
#define DD 768
#define DQ 64
#define HH 3072
#define RR 8192   // BB*SS

// ---------------- scratch (device globals; no allocation allowed) ----------
__device__ float g_h   [RR*DD];
__device__ float g_h2  [RR*DD];
__device__ float g_y1  [RR*DD];
__device__ float g_qkv [RR*256];      // packed q|k|v|pad, row stride 256
__device__ float g_oh  [RR*DQ];
__device__ float g_a1  [(long long)RR*HH];
__device__ float g_ws  [DQ*DD];
__device__ float g_wqkv[DD*256];

__device__ __forceinline__ float to_tf32(float x) {
    float r;
    asm("cvt.rna.tf32.f32 %0, %1;\n" : "=f"(r) : "f"(x));
    return r;
}

__device__ __forceinline__ void cp16(float* dst, const float* src) {
    uint32_t d = (uint32_t)__cvta_generic_to_shared(dst);
    asm volatile("cp.async.cg.shared.global [%0], [%1], 16;\n" :: "r"(d), "l"(src));
}
#define CP_COMMIT() asm volatile("cp.async.commit_group;\n" ::: "memory")
#define CP_WAIT1()  asm volatile("cp.async.wait_group 1;\n" ::: "memory")

__device__ __forceinline__ void mma_tf32(float* c, const uint32_t* a, const uint32_t* b) {
    asm volatile(
        "mma.sync.aligned.m16n8k8.row.col.f32.tf32.tf32.f32 "
        "{%0,%1,%2,%3}, {%4,%5,%6,%7}, {%8,%9}, {%0,%1,%2,%3};\n"
        : "+f"(c[0]), "+f"(c[1]), "+f"(c[2]), "+f"(c[3])
        : "r"(a[0]), "r"(a[1]), "r"(a[2]), "r"(a[3]), "r"(b[0]), "r"(b[1]));
}

// ---------------- block reductions (256 threads) ---------------------------
__device__ __forceinline__ float blk_sum(float v) {
    __shared__ float sm[9];
    #pragma unroll
    for (int o = 16; o; o >>= 1) v += __shfl_xor_sync(0xffffffffu, v, o);
    if ((threadIdx.x & 31) == 0) sm[threadIdx.x >> 5] = v;
    __syncthreads();
    if (threadIdx.x == 0) {
        float t = 0.f;
        #pragma unroll
        for (int i = 0; i < 8; i++) t += sm[i];
        sm[8] = t;
    }
    __syncthreads();
    float r = sm[8];
    __syncthreads();
    return r;
}

// ---------------- small kernels --------------------------------------------
__global__ void wsum_kernel(const float* __restrict__ w, float* __restrict__ d) {
    int i = blockIdx.x * blockDim.x + threadIdx.x;
    if (i >= DQ * DD) return;
    int k = i / DD, n = i % DD;
    float s = 0.f;
    #pragma unroll
    for (int h = 0; h < 12; h++) s += w[(h * DQ + k) * DD + n];
    d[i] = s;
}

__global__ void pack_wqkv_kernel(const float* __restrict__ wq, const float* __restrict__ wk,
                                 const float* __restrict__ wv, float* __restrict__ d) {
    int i = blockIdx.x * blockDim.x + threadIdx.x;
    if (i >= DD * 256) return;
    int r = i >> 8, c = i & 255;
    float v = 0.f;
    if (c < 64)       v = wq[r * 64 + c];
    else if (c < 128) v = wk[r * 64 + c - 64];
    else if (c < 192) v = wv[r * 64 + c - 128];
    d[i] = v;
}

// LayerNorm over 768 cols, fp32 -> fp32. One block / row, 256 threads.
__global__ void ln_kernel(const float* __restrict__ x, const float* __restrict__ g,
                          const float* __restrict__ b, float* __restrict__ o) {
    long long row = blockIdx.x;
    const float* xr = x + row * DD;
    int t = threadIdx.x;
    float v0 = xr[t], v1 = xr[t + 256], v2 = xr[t + 512];
    float mu = blk_sum(v0 + v1 + v2) * (1.f / 768.f);
    float d0 = v0 - mu, d1 = v1 - mu, d2 = v2 - mu;
    float var = blk_sum(d0 * d0 + d1 * d1 + d2 * d2) * (1.f / 768.f);
    float rs = rsqrtf(var + 1e-5f);
    float* orow = o + row * DD;
    orow[t]       = d0 * rs * g[t]       + b[t];
    orow[t + 256] = d1 * rs * g[t + 256] + b[t + 256];
    orow[t + 512] = d2 * rs * g[t + 512] + b[t + 512];
}

// ---------------- pipelined tf32 GEMM --------------------------------------
// C[M,N] = A[M,K] (row) x B[K,N] (row).  EPI: 0 plain, 2 +bias+res, 3 gelu(+bias).
// BM=BN=128, BK=32, 256 threads, cp.async 2-stage. All dims tile-aligned.
#define GEMM_SMEM ((2 * 128 * 36 + 2 * 32 * 136) * 4)

template<int EPI>
__global__ __launch_bounds__(256, 2) void gemm_kernel(
    const float* __restrict__ A, const float* __restrict__ B,
    float* __restrict__ C, const float* __restrict__ bias, const float* __restrict__ res,
    int M, int N, int K, int lda, int ldb, int ldc)
{
    extern __shared__ float smx[];
    float* As = smx;                 // 2 x [128][36]
    float* Bs = smx + 2 * 4608;      // 2 x [32][136]

    const int tid  = threadIdx.x;
    const int lane = tid & 31;
    const int warp = tid >> 5;
    const int wm = (warp >> 2) * 64, wn = (warp & 3) * 32;
    const int grp = lane >> 2, tg = lane & 3;
    const int bm = blockIdx.y * 128, bn = blockIdx.x * 128;
    const int nk = K >> 5;

    const int ar = tid >> 3, ac = (tid & 7) * 4;
    const int kr = tid >> 5, n4 = (tid & 31) * 4;

    float acc[4][4][4];
    #pragma unroll
    for (int i = 0; i < 4; i++)
        #pragma unroll
        for (int j = 0; j < 4; j++)
            #pragma unroll
            for (int l = 0; l < 4; l++) acc[i][j][l] = 0.f;

    auto stage = [&](int i, int st) {
        const int k0 = i << 5;
        float* as = As + st * 4608;
        const float* ap = A + (long long)(bm + ar) * lda + (k0 + ac);
        #pragma unroll
        for (int p = 0; p < 4; p++)
            cp16(&as[(ar + 32 * p) * 36 + ac], ap + (long long)(32 * p) * lda);
        float* bs = Bs + st * 4352;
        const float* bp = B + (long long)(k0 + kr) * ldb + (bn + n4);
        #pragma unroll
        for (int p = 0; p < 4; p++)
            cp16(&bs[(kr + 8 * p) * 136 + n4], bp + (long long)(8 * p) * ldb);
    };

    stage(0, 0);
    CP_COMMIT();

    for (int i = 0; i < nk; i++) {
        if (i + 1 < nk) stage(i + 1, (i + 1) & 1);
        CP_COMMIT();
        CP_WAIT1();
        __syncthreads();

        const float* as = As + (i & 1) * 4608;
        const float* bs = Bs + (i & 1) * 4352;
        #pragma unroll
        for (int ks = 0; ks < 32; ks += 8) {
            uint32_t af[4][4], bfr[4][2];
            #pragma unroll
            for (int mi = 0; mi < 4; mi++) {
                int r = wm + mi * 16 + grp;
                af[mi][0] = __float_as_uint(to_tf32(as[r * 36 + ks + tg]));
                af[mi][1] = __float_as_uint(to_tf32(as[(r + 8) * 36 + ks + tg]));
                af[mi][2] = __float_as_uint(to_tf32(as[r * 36 + ks + tg + 4]));
                af[mi][3] = __float_as_uint(to_tf32(as[(r + 8) * 36 + ks + tg + 4]));
            }
            #pragma unroll
            for (int ni = 0; ni < 4; ni++) {
                int c = wn + ni * 8 + grp;
                bfr[ni][0] = __float_as_uint(to_tf32(bs[(ks + tg) * 136 + c]));
                bfr[ni][1] = __float_as_uint(to_tf32(bs[(ks + tg + 4) * 136 + c]));
            }
            #pragma unroll
            for (int mi = 0; mi < 4; mi++)
                #pragma unroll
                for (int ni = 0; ni < 4; ni++)
                    mma_tf32(acc[mi][ni], af[mi], bfr[ni]);
        }
        __syncthreads();
    }

    #pragma unroll
    for (int mi = 0; mi < 4; mi++) {
        #pragma unroll
        for (int ni = 0; ni < 4; ni++) {
            int c = bn + wn + ni * 8 + 2 * tg;
            #pragma unroll
            for (int rr2 = 0; rr2 < 2; rr2++) {
                int r = bm + wm + mi * 16 + grp + rr2 * 8;
                float v0 = acc[mi][ni][rr2 * 2], v1 = acc[mi][ni][rr2 * 2 + 1];
                long long off = (long long)r * ldc + c;
                if (EPI == 0) {
                    C[off] = v0; C[off + 1] = v1;
                } else if (EPI == 2) {
                    C[off]     = v0 + bias[c]     + res[off];
                    C[off + 1] = v1 + bias[c + 1] + res[off + 1];
                } else {
                    float x0 = v0 + bias[c], x1 = v1 + bias[c + 1];
                    C[off]     = 0.5f * x0 * (1.f + erff(x0 * 0.7071067811865475f));
                    C[off + 1] = 0.5f * x1 * (1.f + erff(x1 * 0.7071067811865475f));
                }
            }
        }
    }
}

// ---------------- flash attention ------------------------------------------
// qkv packed [8192][256] (q|k|v|pad), out g_oh [8192][64].
// Grid (16 q-tiles, 4 batches), 256 thr = 8 warps x 16 q-rows. BKV=128.
#define QS  68
#define KSD 76
#define VSD 72
#define FLASH_SMEM ((128 * QS + 2 * 128 * KSD + 2 * 128 * VSD) * 4)

__global__ __launch_bounds__(256) void flash_kernel(
    const float* __restrict__ qkv, float* __restrict__ oh)
{
    extern __shared__ float smx[];
    float* Qs = smx;                        // [128][68]
    float* Ks = smx + 128 * QS;             // 2 x [128][76]
    float* Vs = Ks + 2 * 128 * KSD;         // 2 x [128][72]

    const int tid = threadIdx.x, lane = tid & 31, warp = tid >> 5;
    const int grp = lane >> 2, tg = lane & 3;
    const int qt = blockIdx.x, batch = blockIdx.y;
    const long long rowbase = (long long)batch * SS;

    auto stage_kv = [&](int t, int st) {
        const float* base = qkv + (rowbase + t * 128) * 256;
        int rid = tid >> 1, half = tid & 1;
        const float* ks = base + rid * 256 + 64 + half * 32;
        float* kd = Ks + st * 128 * KSD + rid * KSD + half * 32;
        #pragma unroll
        for (int j = 0; j < 8; j++) cp16(kd + j * 4, ks + j * 4);
        const float* vs = base + rid * 256 + 128 + half * 32;
        float* vd = Vs + st * 128 * VSD + rid * VSD + half * 32;
        #pragma unroll
        for (int j = 0; j < 8; j++) cp16(vd + j * 4, vs + j * 4);
    };

    stage_kv(0, 0);
    CP_COMMIT();

    // stage Q (scaled by 1/8, tf32-rounded)
    {
        int rid = tid >> 1, half = tid & 1;
        const float* src = qkv + (rowbase + qt * 128 + rid) * 256 + half * 32;
        #pragma unroll
        for (int j = 0; j < 8; j++) {
            float4 v = *(const float4*)(src + j * 4);
            int col = half * 32 + j * 4;
            Qs[rid * QS + col]     = to_tf32(v.x * 0.125f);
            Qs[rid * QS + col + 1] = to_tf32(v.y * 0.125f);
            Qs[rid * QS + col + 2] = to_tf32(v.z * 0.125f);
            Qs[rid * QS + col + 3] = to_tf32(v.w * 0.125f);
        }
    }
    __syncthreads();

    uint32_t qf[8][4];
    {
        int r0 = warp * 16 + grp;
        #pragma unroll
        for (int kc = 0; kc < 8; kc++) {
            qf[kc][0] = __float_as_uint(Qs[r0 * QS + kc * 8 + tg]);
            qf[kc][1] = __float_as_uint(Qs[(r0 + 8) * QS + kc * 8 + tg]);
            qf[kc][2] = __float_as_uint(Qs[r0 * QS + kc * 8 + tg + 4]);
            qf[kc][3] = __float_as_uint(Qs[(r0 + 8) * QS + kc * 8 + tg + 4]);
        }
    }

    float m0 = -1e30f, m1 = -1e30f, l0 = 0.f, l1 = 0.f;
    float oacc[8][4];
    #pragma unroll
    for (int i = 0; i < 8; i++)
        #pragma unroll
        for (int j = 0; j < 4; j++) oacc[i][j] = 0.f;

    for (int t = 0; t < 16; t++) {
        if (t + 1 < 16) stage_kv(t + 1, (t + 1) & 1);
        CP_COMMIT();
        CP_WAIT1();
        __syncthreads();

        const float* K_ = Ks + (t & 1) * 128 * KSD;
        const float* V_ = Vs + (t & 1) * 128 * VSD;

        // S = Q @ K^T
        float sacc[16][4];
        #pragma unroll
        for (int i = 0; i < 16; i++)
            #pragma unroll
            for (int j = 0; j < 4; j++) sacc[i][j] = 0.f;

        #pragma unroll
        for (int kc = 0; kc < 8; kc++) {
            #pragma unroll
            for (int ni = 0; ni < 16; ni++) {
                uint32_t b[2];
                const float* kp = &K_[(ni * 8 + grp) * KSD + kc * 8 + tg];
                b[0] = __float_as_uint(to_tf32(kp[0]));
                b[1] = __float_as_uint(to_tf32(kp[4]));
                mma_tf32(sacc[ni], qf[kc], b);
            }
        }

        // online softmax
        float mt0 = -1e30f, mt1 = -1e30f;
        #pragma unroll
        for (int ni = 0; ni < 16; ni++) {
            mt0 = fmaxf(mt0, fmaxf(sacc[ni][0], sacc[ni][1]));
            mt1 = fmaxf(mt1, fmaxf(sacc[ni][2], sacc[ni][3]));
        }
        mt0 = fmaxf(mt0, __shfl_xor_sync(0xffffffffu, mt0, 1));
        mt0 = fmaxf(mt0, __shfl_xor_sync(0xffffffffu, mt0, 2));
        mt1 = fmaxf(mt1, __shfl_xor_sync(0xffffffffu, mt1, 1));
        mt1 = fmaxf(mt1, __shfl_xor_sync(0xffffffffu, mt1, 2));
        float mn0 = fmaxf(m0, mt0), mn1 = fmaxf(m1, mt1);
        float a0 = __expf(m0 - mn0), a1 = __expf(m1 - mn1);
        float ps0 = 0.f, ps1 = 0.f;
        #pragma unroll
        for (int ni = 0; ni < 16; ni++) {
            sacc[ni][0] = __expf(sacc[ni][0] - mn0); ps0 += sacc[ni][0];
            sacc[ni][1] = __expf(sacc[ni][1] - mn0); ps0 += sacc[ni][1];
            sacc[ni][2] = __expf(sacc[ni][2] - mn1); ps1 += sacc[ni][2];
            sacc[ni][3] = __expf(sacc[ni][3] - mn1); ps1 += sacc[ni][3];
        }
        ps0 += __shfl_xor_sync(0xffffffffu, ps0, 1);
        ps0 += __shfl_xor_sync(0xffffffffu, ps0, 2);
        ps1 += __shfl_xor_sync(0xffffffffu, ps1, 1);
        ps1 += __shfl_xor_sync(0xffffffffu, ps1, 2);
        l0 = l0 * a0 + ps0; l1 = l1 * a1 + ps1;
        m0 = mn0; m1 = mn1;
        #pragma unroll
        for (int dn = 0; dn < 8; dn++) {
            oacc[dn][0] *= a0; oacc[dn][1] *= a0;
            oacc[dn][2] *= a1; oacc[dn][3] *= a1;
        }

        // O += P @ V   (relayout accum -> A-frag via shuffles)
        #pragma unroll
        for (int kc = 0; kc < 16; kc++) {
            const float* c = sacc[kc];
            int s0 = (lane & 28) | (tg >> 1);
            int s1 = s0 + 2;
            float x0 = __shfl_sync(0xffffffffu, c[0], s0);
            float x1 = __shfl_sync(0xffffffffu, c[1], s0);
            float y0 = __shfl_sync(0xffffffffu, c[0], s1);
            float y1 = __shfl_sync(0xffffffffu, c[1], s1);
            float z0 = __shfl_sync(0xffffffffu, c[2], s0);
            float z1 = __shfl_sync(0xffffffffu, c[3], s0);
            float w0 = __shfl_sync(0xffffffffu, c[2], s1);
            float w1 = __shfl_sync(0xffffffffu, c[3], s1);
            bool odd = (tg & 1);
            uint32_t af[4];
            af[0] = __float_as_uint(to_tf32(odd ? x1 : x0));
            af[1] = __float_as_uint(to_tf32(odd ? z1 : z0));
            af[2] = __float_as_uint(to_tf32(odd ? y1 : y0));
            af[3] = __float_as_uint(to_tf32(odd ? w1 : w0));
            #pragma unroll
            for (int dn = 0; dn < 8; dn++) {
                uint32_t b[2];
                const float* vp = &V_[(kc * 8 + tg) * VSD + dn * 8 + grp];
                b[0] = __float_as_uint(to_tf32(vp[0]));
                b[1] = __float_as_uint(to_tf32(vp[4 * VSD]));
                mma_tf32(oacc[dn], af, b);
            }
        }
        __syncthreads();
    }

    // epilogue: O /= l, store
    float i0 = 1.f / l0, i1 = 1.f / l1;
    int r0 = qt * 128 + warp * 16 + grp;
    float* d0 = oh + (rowbase + r0) * DQ;
    float* d1 = oh + (rowbase + r0 + 8) * DQ;
    #pragma unroll
    for (int dn = 0; dn < 8; dn++) {
        int col = dn * 8 + 2 * tg;
        *(float2*)(d0 + col) = make_float2(oacc[dn][0] * i0, oacc[dn][1] * i0);
        *(float2*)(d1 + col) = make_float2(oacc[dn][2] * i1, oacc[dn][3] * i1);
    }
}

// ---------------- launch ----------------------------------------------------
extern "C" void kernel_launch(void* const* d_in, const int* in_sizes, int n_in,
                              void* d_out, int out_size) {
    const float* x    = (const float*)d_in[0];
    const float* wq   = (const float*)d_in[1];
    const float* wk   = (const float*)d_in[2];
    const float* wv   = (const float*)d_in[3];
    const float* linw = (const float*)d_in[4];
    const float* linb = (const float*)d_in[5];
    const float* ln1g = (const float*)d_in[6];
    const float* ln1b = (const float*)d_in[7];
    const float* f1w  = (const float*)d_in[8];
    const float* f1b  = (const float*)d_in[9];
    const float* f2w  = (const float*)d_in[10];
    const float* f2b  = (const float*)d_in[11];
    float* out = (float*)d_out;

    void *p_h, *p_h2, *p_y1, *p_qkv, *p_oh, *p_a1, *p_ws, *p_wqkv;
    cudaGetSymbolAddress(&p_h,    g_h);
    cudaGetSymbolAddress(&p_h2,   g_h2);
    cudaGetSymbolAddress(&p_y1,   g_y1);
    cudaGetSymbolAddress(&p_qkv,  g_qkv);
    cudaGetSymbolAddress(&p_oh,   g_oh);
    cudaGetSymbolAddress(&p_a1,   g_a1);
    cudaGetSymbolAddress(&p_ws,   g_ws);
    cudaGetSymbolAddress(&p_wqkv, g_wqkv);

    cudaFuncSetAttribute(gemm_kernel<0>, cudaFuncAttributeMaxDynamicSharedMemorySize, GEMM_SMEM);
    cudaFuncSetAttribute(gemm_kernel<2>, cudaFuncAttributeMaxDynamicSharedMemorySize, GEMM_SMEM);
    cudaFuncSetAttribute(gemm_kernel<3>, cudaFuncAttributeMaxDynamicSharedMemorySize, GEMM_SMEM);
    cudaFuncSetAttribute(flash_kernel,   cudaFuncAttributeMaxDynamicSharedMemorySize, FLASH_SMEM);

    #define FP(p) ((float*)(p))
    dim3 blk(256);

    wsum_kernel<<<(DQ * DD + 255) / 256, blk>>>(linw, FP(p_ws));
    pack_wqkv_kernel<<<(DD * 256 + 255) / 256, blk>>>(wq, wk, wv, FP(p_wqkv));

    // LN1: x -> h
    ln_kernel<<<RR, blk>>>(x, ln1g, ln1b, FP(p_h));

    // qkv = h @ wqkv_packed   [8192,768]x[768,256]
    gemm_kernel<0><<<dim3(2, 64), blk, GEMM_SMEM>>>(FP(p_h), FP(p_wqkv), FP(p_qkv),
        nullptr, nullptr, RR, 256, DD, DD, 256, 256);

    // flash attention -> oh [8192,64]
    flash_kernel<<<dim3(16, 4), blk, FLASH_SMEM>>>(FP(p_qkv), FP(p_oh));

    // y1 = oh @ W_sum + lin_b + x
    gemm_kernel<2><<<dim3(6, 64), blk, GEMM_SMEM>>>(FP(p_oh), FP(p_ws), FP(p_y1),
        linb, x, RR, DD, DQ, DQ, DD, DD);

    // LN2 (reuses ln1 params, matching reference): y1 -> h2
    ln_kernel<<<RR, blk>>>(FP(p_y1), ln1g, ln1b, FP(p_h2));

    // a1 = gelu(h2 @ fc1_w + fc1_b)
    gemm_kernel<3><<<dim3(24, 64), blk, GEMM_SMEM>>>(FP(p_h2), f1w, FP(p_a1),
        f1b, nullptr, RR, HH, DD, DD, HH, HH);

    // out = a1 @ fc2_w + fc2_b + y1
    gemm_kernel<2><<<dim3(6, 64), blk, GEMM_SMEM>>>(FP(p_a1), f2w, out,
        f2b, FP(p_y1), RR, DD, HH, HH, DD, DD);
    #undef FP
}

// round 4
// speedup vs baseline: 1.5057x; 1.1076x over previous
#include <cuda_runtime.h>
#include <stdint.h>

// Problem dims
#define BB 4
#define SS 2048
#define DD 768
#define DQ 64
#define HH 3072
#define RR 8192   // BB*SS

// ---------------- scratch (device globals; no allocation allowed) ----------
__device__ float g_h   [RR*DD];
__device__ float g_h2  [RR*DD];
__device__ float g_y1  [RR*DD];
__device__ float g_qkv [RR*256];      // packed q|k|v|pad, row stride 256 (tf32-rounded)
__device__ float g_oh  [RR*DQ];
__device__ float g_a1  [(long long)RR*HH];
__device__ float g_ws  [DQ*DD];
__device__ float g_wqkv[DD*256];
__device__ float g_f1  [DD*HH];
__device__ float g_f2  [HH*DD];

__device__ __forceinline__ float to_tf32(float x) {
    float r;
    asm("cvt.rna.tf32.f32 %0, %1;\n" : "=f"(r) : "f"(x));
    return r;
}

__device__ __forceinline__ void cp16(float* dst, const float* src) {
    uint32_t d = (uint32_t)__cvta_generic_to_shared(dst);
    asm volatile("cp.async.cg.shared.global [%0], [%1], 16;\n" :: "r"(d), "l"(src));
}
#define CP_COMMIT() asm volatile("cp.async.commit_group;\n" ::: "memory")
#define CP_WAIT1()  asm volatile("cp.async.wait_group 1;\n" ::: "memory")

__device__ __forceinline__ void mma_tf32(float* c, const uint32_t* a, const uint32_t* b) {
    asm volatile(
        "mma.sync.aligned.m16n8k8.row.col.f32.tf32.tf32.f32 "
        "{%0,%1,%2,%3}, {%4,%5,%6,%7}, {%8,%9}, {%0,%1,%2,%3};\n"
        : "+f"(c[0]), "+f"(c[1]), "+f"(c[2]), "+f"(c[3])
        : "r"(a[0]), "r"(a[1]), "r"(a[2]), "r"(a[3]), "r"(b[0]), "r"(b[1]));
}

// ---------------- block reductions (256 threads) ---------------------------
__device__ __forceinline__ float blk_sum(float v) {
    __shared__ float sm[9];
    #pragma unroll
    for (int o = 16; o; o >>= 1) v += __shfl_xor_sync(0xffffffffu, v, o);
    if ((threadIdx.x & 31) == 0) sm[threadIdx.x >> 5] = v;
    __syncthreads();
    if (threadIdx.x == 0) {
        float t = 0.f;
        #pragma unroll
        for (int i = 0; i < 8; i++) t += sm[i];
        sm[8] = t;
    }
    __syncthreads();
    float r = sm[8];
    __syncthreads();
    return r;
}

// ---------------- small kernels --------------------------------------------
__global__ void wsum_kernel(const float* __restrict__ w, float* __restrict__ d) {
    int i = blockIdx.x * blockDim.x + threadIdx.x;
    if (i >= DQ * DD) return;
    int k = i / DD, n = i % DD;
    float s = 0.f;
    #pragma unroll
    for (int h = 0; h < 12; h++) s += w[(h * DQ + k) * DD + n];
    d[i] = to_tf32(s);
}

__global__ void pack_wqkv_kernel(const float* __restrict__ wq, const float* __restrict__ wk,
                                 const float* __restrict__ wv, float* __restrict__ d) {
    int i = blockIdx.x * blockDim.x + threadIdx.x;
    if (i >= DD * 256) return;
    int r = i >> 8, c = i & 255;
    float v = 0.f;
    if (c < 64)       v = wq[r * 64 + c];
    else if (c < 128) v = wk[r * 64 + c - 64];
    else if (c < 192) v = wv[r * 64 + c - 128];
    d[i] = to_tf32(v);
}

__global__ void round_kernel(const float* __restrict__ s, float* __restrict__ d, int n) {
    int i = blockIdx.x * blockDim.x + threadIdx.x;
    if (i < n) d[i] = to_tf32(s[i]);
}

// LayerNorm over 768 cols, fp32 -> tf32-rounded fp32. One block / row.
__global__ void ln_kernel(const float* __restrict__ x, const float* __restrict__ g,
                          const float* __restrict__ b, float* __restrict__ o) {
    long long row = blockIdx.x;
    const float* xr = x + row * DD;
    int t = threadIdx.x;
    float v0 = xr[t], v1 = xr[t + 256], v2 = xr[t + 512];
    float mu = blk_sum(v0 + v1 + v2) * (1.f / 768.f);
    float d0 = v0 - mu, d1 = v1 - mu, d2 = v2 - mu;
    float var = blk_sum(d0 * d0 + d1 * d1 + d2 * d2) * (1.f / 768.f);
    float rs = rsqrtf(var + 1e-5f);
    float* orow = o + row * DD;
    orow[t]       = to_tf32(d0 * rs * g[t]       + b[t]);
    orow[t + 256] = to_tf32(d1 * rs * g[t + 256] + b[t + 256]);
    orow[t + 512] = to_tf32(d2 * rs * g[t + 512] + b[t + 512]);
}

// ---------------- pipelined tf32 GEMM --------------------------------------
// C[M,N] = A[M,K] x B[K,N], both row-major, both PRE-ROUNDED to tf32.
// EPI: 2 f32 = acc+bias+res, 3 tf32(gelu(acc+bias)), 4 tf32(acc).
#define GEMM_SMEM ((2 * 128 * 36 + 2 * 32 * 136) * 4)

template<int EPI>
__global__ __launch_bounds__(256, 2) void gemm_kernel(
    const float* __restrict__ A, const float* __restrict__ B,
    float* __restrict__ C, const float* __restrict__ bias, const float* __restrict__ res,
    int M, int N, int K, int lda, int ldb, int ldc)
{
    extern __shared__ float smx[];
    float* As = smx;                 // 2 x [128][36]
    float* Bs = smx + 2 * 4608;      // 2 x [32][136]

    const int tid  = threadIdx.x;
    const int lane = tid & 31;
    const int warp = tid >> 5;
    const int wm = (warp >> 2) * 64, wn = (warp & 3) * 32;
    const int grp = lane >> 2, tg = lane & 3;
    const int bm = blockIdx.y * 128, bn = blockIdx.x * 128;
    const int nk = K >> 5;

    const int ar = tid >> 3, ac = (tid & 7) * 4;
    const int kr = tid >> 5, n4 = (tid & 31) * 4;

    float acc[4][4][4];
    #pragma unroll
    for (int i = 0; i < 4; i++)
        #pragma unroll
        for (int j = 0; j < 4; j++)
            #pragma unroll
            for (int l = 0; l < 4; l++) acc[i][j][l] = 0.f;

    auto stage = [&](int i, int st) {
        const int k0 = i << 5;
        float* as = As + st * 4608;
        const float* ap = A + (long long)(bm + ar) * lda + (k0 + ac);
        #pragma unroll
        for (int p = 0; p < 4; p++)
            cp16(&as[(ar + 32 * p) * 36 + ac], ap + (long long)(32 * p) * lda);
        float* bs = Bs + st * 4352;
        const float* bp = B + (long long)(k0 + kr) * ldb + (bn + n4);
        #pragma unroll
        for (int p = 0; p < 4; p++)
            cp16(&bs[(kr + 8 * p) * 136 + n4], bp + (long long)(8 * p) * ldb);
    };

    stage(0, 0);
    CP_COMMIT();

    for (int i = 0; i < nk; i++) {
        if (i + 1 < nk) stage(i + 1, (i + 1) & 1);
        CP_COMMIT();
        CP_WAIT1();
        __syncthreads();

        const float* as = As + (i & 1) * 4608;
        const float* bs = Bs + (i & 1) * 4352;
        #pragma unroll
        for (int ks = 0; ks < 32; ks += 8) {
            uint32_t af[4][4], bfr[4][2];
            #pragma unroll
            for (int mi = 0; mi < 4; mi++) {
                int r = wm + mi * 16 + grp;
                af[mi][0] = __float_as_uint(as[r * 36 + ks + tg]);
                af[mi][1] = __float_as_uint(as[(r + 8) * 36 + ks + tg]);
                af[mi][2] = __float_as_uint(as[r * 36 + ks + tg + 4]);
                af[mi][3] = __float_as_uint(as[(r + 8) * 36 + ks + tg + 4]);
            }
            #pragma unroll
            for (int ni = 0; ni < 4; ni++) {
                int c = wn + ni * 8 + grp;
                bfr[ni][0] = __float_as_uint(bs[(ks + tg) * 136 + c]);
                bfr[ni][1] = __float_as_uint(bs[(ks + tg + 4) * 136 + c]);
            }
            #pragma unroll
            for (int mi = 0; mi < 4; mi++)
                #pragma unroll
                for (int ni = 0; ni < 4; ni++)
                    mma_tf32(acc[mi][ni], af[mi], bfr[ni]);
        }
        __syncthreads();
    }

    #pragma unroll
    for (int mi = 0; mi < 4; mi++) {
        #pragma unroll
        for (int ni = 0; ni < 4; ni++) {
            int c = bn + wn + ni * 8 + 2 * tg;
            #pragma unroll
            for (int rr2 = 0; rr2 < 2; rr2++) {
                int r = bm + wm + mi * 16 + grp + rr2 * 8;
                float v0 = acc[mi][ni][rr2 * 2], v1 = acc[mi][ni][rr2 * 2 + 1];
                long long off = (long long)r * ldc + c;
                if (EPI == 2) {
                    C[off]     = v0 + bias[c]     + res[off];
                    C[off + 1] = v1 + bias[c + 1] + res[off + 1];
                } else if (EPI == 3) {
                    float x0 = v0 + bias[c], x1 = v1 + bias[c + 1];
                    C[off]     = to_tf32(0.5f * x0 * (1.f + erff(x0 * 0.7071067811865475f)));
                    C[off + 1] = to_tf32(0.5f * x1 * (1.f + erff(x1 * 0.7071067811865475f)));
                } else {
                    C[off] = to_tf32(v0); C[off + 1] = to_tf32(v1);
                }
            }
        }
    }
}

// ---------------- flash attention ------------------------------------------
// qkv packed [8192][256] (q|k|v|pad, tf32-rounded), out g_oh [8192][64] (rounded).
// BQ=64, BKV=64, 128 threads = 4 warps x 16 q-rows. Grid (32 q-tiles, 4 batches).
#define QS  68
#define KSD 76
#define VSD 72
#define FLASH_SMEM ((64 * QS + 2 * 64 * KSD + 2 * 64 * VSD) * 4)

__global__ __launch_bounds__(128, 2) void flash_kernel(
    const float* __restrict__ qkv, float* __restrict__ oh)
{
    extern __shared__ float smx[];
    float* Qs = smx;                        // [64][68]
    float* Ks = smx + 64 * QS;              // 2 x [64][76]
    float* Vs = Ks + 2 * 64 * KSD;          // 2 x [64][72]

    const int tid = threadIdx.x, lane = tid & 31, warp = tid >> 5;
    const int grp = lane >> 2, tg = lane & 3;
    const int qt = blockIdx.x, batch = blockIdx.y;
    const long long rowbase = (long long)batch * SS;

    auto stage_kv = [&](int t, int st) {
        const float* base = qkv + (rowbase + t * 64) * 256;
        int rid = tid >> 1, half = tid & 1;
        const float* ks = base + rid * 256 + 64 + half * 32;
        float* kd = Ks + st * 64 * KSD + rid * KSD + half * 32;
        #pragma unroll
        for (int j = 0; j < 8; j++) cp16(kd + j * 4, ks + j * 4);
        const float* vs = base + rid * 256 + 128 + half * 32;
        float* vd = Vs + st * 64 * VSD + rid * VSD + half * 32;
        #pragma unroll
        for (int j = 0; j < 8; j++) cp16(vd + j * 4, vs + j * 4);
    };

    stage_kv(0, 0);
    CP_COMMIT();

    // stage Q (scale by 1/8 = exact exponent shift; values stay tf32)
    {
        int rid = tid >> 1, half = tid & 1;
        const float* src = qkv + (rowbase + qt * 64 + rid) * 256 + half * 32;
        #pragma unroll
        for (int j = 0; j < 8; j++) {
            float4 v = *(const float4*)(src + j * 4);
            int col = half * 32 + j * 4;
            Qs[rid * QS + col]     = v.x * 0.125f;
            Qs[rid * QS + col + 1] = v.y * 0.125f;
            Qs[rid * QS + col + 2] = v.z * 0.125f;
            Qs[rid * QS + col + 3] = v.w * 0.125f;
        }
    }
    __syncthreads();

    uint32_t qf[8][4];
    {
        int r0 = warp * 16 + grp;
        #pragma unroll
        for (int kc = 0; kc < 8; kc++) {
            qf[kc][0] = __float_as_uint(Qs[r0 * QS + kc * 8 + tg]);
            qf[kc][1] = __float_as_uint(Qs[(r0 + 8) * QS + kc * 8 + tg]);
            qf[kc][2] = __float_as_uint(Qs[r0 * QS + kc * 8 + tg + 4]);
            qf[kc][3] = __float_as_uint(Qs[(r0 + 8) * QS + kc * 8 + tg + 4]);
        }
    }

    float m0 = -1e30f, m1 = -1e30f, l0 = 0.f, l1 = 0.f;
    float oacc[8][4];
    #pragma unroll
    for (int i = 0; i < 8; i++)
        #pragma unroll
        for (int j = 0; j < 4; j++) oacc[i][j] = 0.f;

    for (int t = 0; t < 32; t++) {
        if (t + 1 < 32) stage_kv(t + 1, (t + 1) & 1);
        CP_COMMIT();
        CP_WAIT1();
        __syncthreads();

        const float* K_ = Ks + (t & 1) * 64 * KSD;
        const float* V_ = Vs + (t & 1) * 64 * VSD;

        // S = Q @ K^T  (64 cols)
        float sacc[8][4];
        #pragma unroll
        for (int i = 0; i < 8; i++)
            #pragma unroll
            for (int j = 0; j < 4; j++) sacc[i][j] = 0.f;

        #pragma unroll
        for (int kc = 0; kc < 8; kc++) {
            #pragma unroll
            for (int ni = 0; ni < 8; ni++) {
                uint32_t b[2];
                const float* kp = &K_[(ni * 8 + grp) * KSD + kc * 8 + tg];
                b[0] = __float_as_uint(kp[0]);
                b[1] = __float_as_uint(kp[4]);
                mma_tf32(sacc[ni], qf[kc], b);
            }
        }

        // online softmax
        float mt0 = -1e30f, mt1 = -1e30f;
        #pragma unroll
        for (int ni = 0; ni < 8; ni++) {
            mt0 = fmaxf(mt0, fmaxf(sacc[ni][0], sacc[ni][1]));
            mt1 = fmaxf(mt1, fmaxf(sacc[ni][2], sacc[ni][3]));
        }
        mt0 = fmaxf(mt0, __shfl_xor_sync(0xffffffffu, mt0, 1));
        mt0 = fmaxf(mt0, __shfl_xor_sync(0xffffffffu, mt0, 2));
        mt1 = fmaxf(mt1, __shfl_xor_sync(0xffffffffu, mt1, 1));
        mt1 = fmaxf(mt1, __shfl_xor_sync(0xffffffffu, mt1, 2));
        float mn0 = fmaxf(m0, mt0), mn1 = fmaxf(m1, mt1);
        float a0 = __expf(m0 - mn0), a1 = __expf(m1 - mn1);
        float ps0 = 0.f, ps1 = 0.f;
        #pragma unroll
        for (int ni = 0; ni < 8; ni++) {
            sacc[ni][0] = __expf(sacc[ni][0] - mn0); ps0 += sacc[ni][0];
            sacc[ni][1] = __expf(sacc[ni][1] - mn0); ps0 += sacc[ni][1];
            sacc[ni][2] = __expf(sacc[ni][2] - mn1); ps1 += sacc[ni][2];
            sacc[ni][3] = __expf(sacc[ni][3] - mn1); ps1 += sacc[ni][3];
        }
        ps0 += __shfl_xor_sync(0xffffffffu, ps0, 1);
        ps0 += __shfl_xor_sync(0xffffffffu, ps0, 2);
        ps1 += __shfl_xor_sync(0xffffffffu, ps1, 1);
        ps1 += __shfl_xor_sync(0xffffffffu, ps1, 2);
        l0 = l0 * a0 + ps0; l1 = l1 * a1 + ps1;
        m0 = mn0; m1 = mn1;
        #pragma unroll
        for (int dn = 0; dn < 8; dn++) {
            oacc[dn][0] *= a0; oacc[dn][1] *= a0;
            oacc[dn][2] *= a1; oacc[dn][3] *= a1;
        }

        // O += P @ V  (P raw fp32 -> HW tf32 truncation; V pre-rounded)
        #pragma unroll
        for (int kc = 0; kc < 8; kc++) {
            const float* c = sacc[kc];
            int s0 = (lane & 28) | (tg >> 1);
            int s1 = s0 + 2;
            float x0 = __shfl_sync(0xffffffffu, c[0], s0);
            float x1 = __shfl_sync(0xffffffffu, c[1], s0);
            float y0 = __shfl_sync(0xffffffffu, c[0], s1);
            float y1 = __shfl_sync(0xffffffffu, c[1], s1);
            float z0 = __shfl_sync(0xffffffffu, c[2], s0);
            float z1 = __shfl_sync(0xffffffffu, c[3], s0);
            float w0 = __shfl_sync(0xffffffffu, c[2], s1);
            float w1 = __shfl_sync(0xffffffffu, c[3], s1);
            bool odd = (tg & 1);
            uint32_t af[4];
            af[0] = __float_as_uint(odd ? x1 : x0);
            af[1] = __float_as_uint(odd ? z1 : z0);
            af[2] = __float_as_uint(odd ? y1 : y0);
            af[3] = __float_as_uint(odd ? w1 : w0);
            #pragma unroll
            for (int dn = 0; dn < 8; dn++) {
                uint32_t b[2];
                const float* vp = &V_[(kc * 8 + tg) * VSD + dn * 8 + grp];
                b[0] = __float_as_uint(vp[0]);
                b[1] = __float_as_uint(vp[4 * VSD]);
                mma_tf32(oacc[dn], af, b);
            }
        }
        __syncthreads();
    }

    // epilogue: O /= l, tf32-round, store
    float i0 = 1.f / l0, i1 = 1.f / l1;
    int r0 = qt * 64 + warp * 16 + grp;
    float* d0 = oh + (rowbase + r0) * DQ;
    float* d1 = oh + (rowbase + r0 + 8) * DQ;
    #pragma unroll
    for (int dn = 0; dn < 8; dn++) {
        int col = dn * 8 + 2 * tg;
        *(float2*)(d0 + col) = make_float2(to_tf32(oacc[dn][0] * i0), to_tf32(oacc[dn][1] * i0));
        *(float2*)(d1 + col) = make_float2(to_tf32(oacc[dn][2] * i1), to_tf32(oacc[dn][3] * i1));
    }
}

// ---------------- launch ----------------------------------------------------
extern "C" void kernel_launch(void* const* d_in, const int* in_sizes, int n_in,
                              void* d_out, int out_size) {
    const float* x    = (const float*)d_in[0];
    const float* wq   = (const float*)d_in[1];
    const float* wk   = (const float*)d_in[2];
    const float* wv   = (const float*)d_in[3];
    const float* linw = (const float*)d_in[4];
    const float* linb = (const float*)d_in[5];
    const float* ln1g = (const float*)d_in[6];
    const float* ln1b = (const float*)d_in[7];
    const float* f1w  = (const float*)d_in[8];
    const float* f1b  = (const float*)d_in[9];
    const float* f2w  = (const float*)d_in[10];
    const float* f2b  = (const float*)d_in[11];
    float* out = (float*)d_out;

    void *p_h, *p_h2, *p_y1, *p_qkv, *p_oh, *p_a1, *p_ws, *p_wqkv, *p_f1, *p_f2;
    cudaGetSymbolAddress(&p_h,    g_h);
    cudaGetSymbolAddress(&p_h2,   g_h2);
    cudaGetSymbolAddress(&p_y1,   g_y1);
    cudaGetSymbolAddress(&p_qkv,  g_qkv);
    cudaGetSymbolAddress(&p_oh,   g_oh);
    cudaGetSymbolAddress(&p_a1,   g_a1);
    cudaGetSymbolAddress(&p_ws,   g_ws);
    cudaGetSymbolAddress(&p_wqkv, g_wqkv);
    cudaGetSymbolAddress(&p_f1,   g_f1);
    cudaGetSymbolAddress(&p_f2,   g_f2);

    cudaFuncSetAttribute(gemm_kernel<2>, cudaFuncAttributeMaxDynamicSharedMemorySize, GEMM_SMEM);
    cudaFuncSetAttribute(gemm_kernel<3>, cudaFuncAttributeMaxDynamicSharedMemorySize, GEMM_SMEM);
    cudaFuncSetAttribute(gemm_kernel<4>, cudaFuncAttributeMaxDynamicSharedMemorySize, GEMM_SMEM);
    cudaFuncSetAttribute(flash_kernel,   cudaFuncAttributeMaxDynamicSharedMemorySize, FLASH_SMEM);

    #define FP(p) ((float*)(p))
    dim3 blk(256);

    wsum_kernel<<<(DQ * DD + 255) / 256, blk>>>(linw, FP(p_ws));
    pack_wqkv_kernel<<<(DD * 256 + 255) / 256, blk>>>(wq, wk, wv, FP(p_wqkv));
    round_kernel<<<(DD * HH + 255) / 256, blk>>>(f1w, FP(p_f1), DD * HH);
    round_kernel<<<(HH * DD + 255) / 256, blk>>>(f2w, FP(p_f2), HH * DD);

    // LN1: x -> h (tf32)
    ln_kernel<<<RR, blk>>>(x, ln1g, ln1b, FP(p_h));

    // qkv = h @ wqkv_packed, tf32-rounded store
    gemm_kernel<4><<<dim3(2, 64), blk, GEMM_SMEM>>>(FP(p_h), FP(p_wqkv), FP(p_qkv),
        nullptr, nullptr, RR, 256, DD, DD, 256, 256);

    // flash attention -> oh [8192,64] (tf32)
    flash_kernel<<<dim3(32, 4), dim3(128), FLASH_SMEM>>>(FP(p_qkv), FP(p_oh));

    // y1 = oh @ W_sum + lin_b + x  (fp32)
    gemm_kernel<2><<<dim3(6, 64), blk, GEMM_SMEM>>>(FP(p_oh), FP(p_ws), FP(p_y1),
        linb, x, RR, DD, DQ, DQ, DD, DD);

    // LN2 (reuses ln1 params, matching reference): y1 -> h2 (tf32)
    ln_kernel<<<RR, blk>>>(FP(p_y1), ln1g, ln1b, FP(p_h2));

    // a1 = gelu(h2 @ fc1_w + fc1_b)  (tf32)
    gemm_kernel<3><<<dim3(24, 64), blk, GEMM_SMEM>>>(FP(p_h2), FP(p_f1), FP(p_a1),
        f1b, nullptr, RR, HH, DD, DD, HH, HH);

    // out = a1 @ fc2_w + fc2_b + y1  (fp32)
    gemm_kernel<2><<<dim3(6, 64), blk, GEMM_SMEM>>>(FP(p_a1), FP(p_f2), out,
        f2b, FP(p_y1), RR, DD, HH, HH, DD, DD);
    #undef FP
}